// round 8
// baseline (speedup 1.0000x reference)
#include <cuda_runtime.h>

// out[b, i] = x[b, i] * diagonal[i]
// x: [8192, 4096] f32, diagonal: [4096] f32, out: [8192, 4096] f32
//
// Final: R4 layout (best measured kernel time, 36.00us @ 80.4% occ) with
// write-through stores. Each thread owns ONE float4 column and 4 consecutive
// rows; diagonal loaded once per thread; 4 front-batched streaming loads;
// st.global.wt streams outputs toward DRAM without L2 dirty-line writeback.

static constexpr int SIZE     = 4096;
static constexpr int BATCH    = 8192;
static constexpr int SIZE_V4  = SIZE / 4;              // 1024 float4 per row
static constexpr int THREADS  = 256;
static constexpr int COL_CHUNKS = SIZE_V4 / THREADS;   // 4
static constexpr int ROWS_PER_THREAD = 4;
static constexpr int ROW_BLOCKS = BATCH / ROWS_PER_THREAD;  // 2048

__device__ __forceinline__ void stg128_wt(float4* p, const float4& v) {
    asm volatile("st.global.wt.v4.f32 [%0], {%1,%2,%3,%4};"
                 :: "l"(p), "f"(v.x), "f"(v.y), "f"(v.z), "f"(v.w)
                 : "memory");
}

__global__ __launch_bounds__(THREADS)
void diag_scale_kernel(const float4* __restrict__ x,
                       const float4* __restrict__ diag,
                       float4* __restrict__ out)
{
    // blockIdx.x = row_block * COL_CHUNKS + col_chunk
    const int col_chunk = blockIdx.x & (COL_CHUNKS - 1);
    const int row_block = blockIdx.x >> 2;            // / COL_CHUNKS

    const int c = col_chunk * THREADS + threadIdx.x;  // float4 column
    const float4 dv = __ldg(&diag[c]);                // ONE diag load per thread

    const long long base =
        (long long)row_block * ROWS_PER_THREAD * SIZE_V4 + c;

    // Front-batched independent loads: MLP = 4
    float4 xv[ROWS_PER_THREAD];
#pragma unroll
    for (int k = 0; k < ROWS_PER_THREAD; k++)
        xv[k] = __ldcs(&x[base + (long long)k * SIZE_V4]);

#pragma unroll
    for (int k = 0; k < ROWS_PER_THREAD; k++) {
        float4 ov;
        ov.x = xv[k].x * dv.x;
        ov.y = xv[k].y * dv.y;
        ov.z = xv[k].z * dv.z;
        ov.w = xv[k].w * dv.w;
        stg128_wt(&out[base + (long long)k * SIZE_V4], ov);
    }
}

extern "C" void kernel_launch(void* const* d_in, const int* in_sizes, int n_in,
                              void* d_out, int out_size)
{
    const float4* x    = (const float4*)d_in[0];
    const float4* diag = (const float4*)d_in[1];
    float4*       out  = (float4*)d_out;

    const int blocks = ROW_BLOCKS * COL_CHUNKS;   // 8192
    diag_scale_kernel<<<blocks, THREADS>>>(x, diag, out);
}

// round 9
// speedup vs baseline: 1.0044x; 1.0044x over previous
#include <cuda_runtime.h>

// out[b, i] = x[b, i] * diagonal[i]
// x: [8192, 4096] f32, diagonal: [4096] f32, out: [8192, 4096] f32
//
// FINAL: memory-roofline streaming kernel. Measured plateau across 7 layout
// variants: ~5.9 TB/s (DRAM 74-75%), kernel ~36.0us — the effective mixed
// 1:1 read/write HBM ceiling on GB300 (LTS cap is path-independent, so TMA
// cannot beat this either).
//
// Layout: each thread owns ONE float4 column and 4 consecutive rows.
//  - diagonal loaded once per thread (no per-element diag loads)
//  - 4 front-batched independent streaming loads (MLP=4)
//  - evict-streaming hints on both read-once and write-once streams
//  - 28 regs, THREADS=512 -> 48 warps/SM, fewer CTAs, 8KiB bursts/warp-group

static constexpr int SIZE     = 4096;
static constexpr int BATCH    = 8192;
static constexpr int SIZE_V4  = SIZE / 4;              // 1024 float4 per row
static constexpr int THREADS  = 512;
static constexpr int COL_CHUNKS = SIZE_V4 / THREADS;   // 2
static constexpr int ROWS_PER_THREAD = 4;
static constexpr int ROW_BLOCKS = BATCH / ROWS_PER_THREAD;  // 2048

__global__ __launch_bounds__(THREADS)
void diag_scale_kernel(const float4* __restrict__ x,
                       const float4* __restrict__ diag,
                       float4* __restrict__ out)
{
    // blockIdx.x = row_block * COL_CHUNKS + col_chunk
    const int col_chunk = blockIdx.x & (COL_CHUNKS - 1);
    const int row_block = blockIdx.x >> 1;            // / COL_CHUNKS

    const int c = col_chunk * THREADS + threadIdx.x;  // float4 column
    const float4 dv = __ldg(&diag[c]);                // ONE diag load per thread

    const long long base =
        (long long)row_block * ROWS_PER_THREAD * SIZE_V4 + c;

    // Front-batched independent loads: MLP = 4
    float4 xv[ROWS_PER_THREAD];
#pragma unroll
    for (int k = 0; k < ROWS_PER_THREAD; k++)
        xv[k] = __ldcs(&x[base + (long long)k * SIZE_V4]);

#pragma unroll
    for (int k = 0; k < ROWS_PER_THREAD; k++) {
        float4 ov;
        ov.x = xv[k].x * dv.x;
        ov.y = xv[k].y * dv.y;
        ov.z = xv[k].z * dv.z;
        ov.w = xv[k].w * dv.w;
        __stcs(&out[base + (long long)k * SIZE_V4], ov);
    }
}

extern "C" void kernel_launch(void* const* d_in, const int* in_sizes, int n_in,
                              void* d_out, int out_size)
{
    const float4* x    = (const float4*)d_in[0];
    const float4* diag = (const float4*)d_in[1];
    float4*       out  = (float4*)d_out;

    const int blocks = ROW_BLOCKS * COL_CHUNKS;   // 4096
    diag_scale_kernel<<<blocks, THREADS>>>(x, diag, out);
}